// round 15
// baseline (speedup 1.0000x reference)
#include <cuda_runtime.h>
#include <math.h>

// ---------------------------------------------------------------------------
// PeriodicEncoder: 3x Conv1d(K=15, same) + train-mode BN + ELU, DFT spectral
// stats, batch-normalized phase head.  B=65536, Cin=48, L=15.
//
// R14: conv2 restructured to 2 output channels per thread (384 thr = 64
// samples x 6 groups x 2 co). 15 x-loads now feed 338 FFMAs; per-warp ILP
// doubles. conv1/conv3 unchanged from R13 (best known).
// ---------------------------------------------------------------------------

#define HOR   15
#define CIN1  48
#define COUT1 48
#define COUT2 12
#define LATD  6
#define BMAX  65536

__device__ float  g_y1[(size_t)COUT1 * HOR * BMAX];   // conv1 raw output, [720][B]
__device__ float  g_y2[(size_t)COUT2 * HOR * BMAX];   // conv2 raw output, [180][B]
__device__ float  g_v [(size_t)LATD * 2 * BMAX];      // phase-head pre-BN, [12][B]

__device__ double g_sum1[COUT1], g_ssq1[COUT1];
__device__ double g_sum2[COUT2], g_ssq2[COUT2];
__device__ double g_vsum[LATD * 2], g_vssq[LATD * 2];

__device__ float  g_scale1[COUT1], g_shift1[COUT1];
__device__ float  g_scale2[COUT2], g_shift2[COUT2];
__device__ float  g_vscale[LATD * 2], g_vshift[LATD * 2];

// ---------------------------------------------------------------------------
__global__ void k_zero()
{
    int t = threadIdx.x;
    if (t < COUT1) { g_sum1[t] = 0.0; g_ssq1[t] = 0.0; }
    if (t < COUT2) {
        g_sum2[t] = 0.0; g_ssq2[t] = 0.0;
        g_vsum[t] = 0.0; g_vssq[t] = 0.0;
    }
}

// ---------------------------------------------------------------------------
// Inner conv micro-kernel: 48 input channels, one output channel.
// ---------------------------------------------------------------------------
__device__ __forceinline__ void conv48(const float* __restrict__ xrow,
                                       const float4* __restrict__ wv4,
                                       float acc[15])
{
    for (int ci = 0; ci < 48; ++ci) {
        float xv[15];
#pragma unroll
        for (int m = 0; m < 15; ++m) xv[m] = xrow[ci * 15 + m];

        float4 w0 = wv4[ci * 4 + 0];
        float4 w1 = wv4[ci * 4 + 1];
        float4 w2 = wv4[ci * 4 + 2];
        float4 w3 = wv4[ci * 4 + 3];
        float wv[15];
        wv[0]=w0.x; wv[1]=w0.y; wv[2]=w0.z; wv[3]=w0.w;
        wv[4]=w1.x; wv[5]=w1.y; wv[6]=w1.z; wv[7]=w1.w;
        wv[8]=w2.x; wv[9]=w2.y; wv[10]=w2.z; wv[11]=w2.w;
        wv[12]=w3.x; wv[13]=w3.y; wv[14]=w3.z;

#pragma unroll
        for (int m = 0; m < 15; ++m) {
#pragma unroll
            for (int l = 0; l < 15; ++l) {
                int k = m - l + 7;
                if (k >= 0 && k < 15)
                    acc[l] = fmaf(wv[k], xv[m], acc[l]);
            }
        }
    }
}

// ---------------------------------------------------------------------------
// Kernel 1: conv1 (48->48, K=15) + BN1 statistics.  (unchanged from R13)
// 768 threads = 64 samples x 12 co-groups; 4 weight chunks of 12 co.
// ---------------------------------------------------------------------------
__global__ void __launch_bounds__(768, 1)
k_conv1(const float* __restrict__ x, const float* __restrict__ w1,
        const float* __restrict__ b1, int B)
{
    extern __shared__ float sm[];
    float* xs = sm;                 // 64 * 721  (odd stride -> conflict-free)
    float* ws = sm + 64 * 721;      // 12 * 48 * 16 (padded rows, 16B aligned)

    const int tid = threadIdx.x;
    const int s   = tid & 63;
    const int cg  = tid >> 6;       // 0..11
    const int b0  = blockIdx.x * 64;

    for (int idx = tid; idx < 64 * 720; idx += 768) {
        int ss = idx / 720, i = idx - ss * 720;
        int b  = b0 + ss;
        xs[ss * 721 + i] = (b < B) ? x[(size_t)b * 720 + i] : 0.f;
    }

    const int  b     = b0 + s;
    const bool valid = (b < B);
    const float* xrow = xs + s * 721;
    const float4* wv4 = reinterpret_cast<const float4*>(ws) + cg * 48 * 4;

    for (int chunk = 0; chunk < 4; ++chunk) {
        __syncthreads();
        const float* wsrc = w1 + (size_t)chunk * 12 * 720;
        for (int idx = tid; idx < 12 * 720; idx += 768) {
            int r = idx / 15, k = idx - r * 15;
            ws[r * 16 + k] = wsrc[idx];
        }
        __syncthreads();

        float acc[15];
#pragma unroll
        for (int l = 0; l < 15; ++l) acc[l] = 0.f;

        conv48(xrow, wv4, acc);

        const int   co   = chunk * 12 + cg;
        const float bias = b1[co];
        float ps = 0.f, ps2 = 0.f;
#pragma unroll
        for (int l = 0; l < 15; ++l) {
            float yv = acc[l] + bias;
            if (valid) g_y1[(size_t)(co * 15 + l) * B + b] = yv;
            ps  += yv;
            ps2  = fmaf(yv, yv, ps2);
        }
        if (!valid) { ps = 0.f; ps2 = 0.f; }
#pragma unroll
        for (int off = 16; off; off >>= 1) {
            ps  += __shfl_down_sync(0xffffffffu, ps,  off);
            ps2 += __shfl_down_sync(0xffffffffu, ps2, off);
        }
        if ((tid & 31) == 0) {
            atomicAdd(&g_sum1[co], (double)ps);
            atomicAdd(&g_ssq1[co], (double)ps2);
        }
    }
}

// ---------------------------------------------------------------------------
// BN finalize: scale = g * rsqrt(var + 1e-5), shift = beta - mean * scale
// ---------------------------------------------------------------------------
__global__ void k_finalize(const float* __restrict__ g,
                           const float* __restrict__ bb,
                           int which, int C, double invN)
{
    int c = threadIdx.x;
    if (c >= C) return;
    double su, sq; float* sc; float* sh;
    if (which == 0)      { su = g_sum1[c]; sq = g_ssq1[c]; sc = g_scale1; sh = g_shift1; }
    else if (which == 1) { su = g_sum2[c]; sq = g_ssq2[c]; sc = g_scale2; sh = g_shift2; }
    else                 { su = g_vsum[c]; sq = g_vssq[c]; sc = g_vscale; sh = g_vshift; }
    double m   = su * invN;
    double var = sq * invN - m * m;
    double rs  = 1.0 / sqrt(var + 1e-5);
    double scl = (double)g[c] * rs;
    sc[c] = (float)scl;
    sh[c] = (float)((double)bb[c] - m * scl);
}

// ---------------------------------------------------------------------------
// Kernel 3: h1 = ELU(BN1(y1)); conv2 (48->12) + BN2 statistics.
// R14: 384 threads = 64 samples x 6 groups x 2 co per thread.
// smem 219KB -> 1 block/SM, 12 warps; 338 FFMA per 15 x-loads.
// ---------------------------------------------------------------------------
__global__ void __launch_bounds__(384, 1)
k_conv2(const float* __restrict__ w2, const float* __restrict__ b2, int B)
{
    extern __shared__ float sm[];
    float* xs  = sm;                   // 64 * 721
    float* ws  = sm + 64 * 721;        // 12 * 48 * 16 (padded)
    float* ssc = ws + 12 * 48 * 16;    // 48
    float* ssh = ssc + 48;             // 48

    const int tid = threadIdx.x;
    if (tid < 48) { ssc[tid] = g_scale1[tid]; ssh[tid] = g_shift1[tid]; }
    for (int idx = tid; idx < 12 * 720; idx += 384) {
        int r = idx / 15, k = idx - r * 15;
        ws[r * 16 + k] = w2[idx];
    }
    __syncthreads();

    const int b0 = blockIdx.x * 64;
    for (int idx = tid; idx < 64 * 720; idx += 384) {
        int s2 = idx & 63, i = idx >> 6;
        int bb = b0 + s2;
        float h = 0.f;
        if (bb < B) {
            float yv = g_y1[(size_t)i * B + bb];
            int   co = i / 15;
            float z  = fmaf(yv, ssc[co], ssh[co]);
            h = (z > 0.f) ? z : expm1f(z);
        }
        xs[s2 * 721 + i] = h;
    }
    __syncthreads();

    const int  s     = tid & 63;
    const int  g     = tid >> 6;       // 0..5
    const int  co0   = 2 * g;
    const int  b     = b0 + s;
    const bool valid = (b < B);
    const float* xrow  = xs + s * 721;
    const float4* wv4a = reinterpret_cast<const float4*>(ws) + (co0 + 0) * 48 * 4;
    const float4* wv4b = reinterpret_cast<const float4*>(ws) + (co0 + 1) * 48 * 4;

    float acc0[15], acc1[15];
#pragma unroll
    for (int l = 0; l < 15; ++l) { acc0[l] = 0.f; acc1[l] = 0.f; }

    for (int ci = 0; ci < 48; ++ci) {
        float xv[15];
#pragma unroll
        for (int m = 0; m < 15; ++m) xv[m] = xrow[ci * 15 + m];

        float4 a0 = wv4a[ci * 4 + 0];
        float4 a1 = wv4a[ci * 4 + 1];
        float4 a2 = wv4a[ci * 4 + 2];
        float4 a3 = wv4a[ci * 4 + 3];
        float wa[15];
        wa[0]=a0.x; wa[1]=a0.y; wa[2]=a0.z; wa[3]=a0.w;
        wa[4]=a1.x; wa[5]=a1.y; wa[6]=a1.z; wa[7]=a1.w;
        wa[8]=a2.x; wa[9]=a2.y; wa[10]=a2.z; wa[11]=a2.w;
        wa[12]=a3.x; wa[13]=a3.y; wa[14]=a3.z;

        float4 c0 = wv4b[ci * 4 + 0];
        float4 c1 = wv4b[ci * 4 + 1];
        float4 c2 = wv4b[ci * 4 + 2];
        float4 c3 = wv4b[ci * 4 + 3];
        float wb[15];
        wb[0]=c0.x; wb[1]=c0.y; wb[2]=c0.z; wb[3]=c0.w;
        wb[4]=c1.x; wb[5]=c1.y; wb[6]=c1.z; wb[7]=c1.w;
        wb[8]=c2.x; wb[9]=c2.y; wb[10]=c2.z; wb[11]=c2.w;
        wb[12]=c3.x; wb[13]=c3.y; wb[14]=c3.z;

#pragma unroll
        for (int m = 0; m < 15; ++m) {
#pragma unroll
            for (int l = 0; l < 15; ++l) {
                int k = m - l + 7;
                if (k >= 0 && k < 15) {
                    acc0[l] = fmaf(wa[k], xv[m], acc0[l]);
                    acc1[l] = fmaf(wb[k], xv[m], acc1[l]);
                }
            }
        }
    }

#pragma unroll
    for (int j = 0; j < 2; ++j) {
        const int   co   = co0 + j;
        const float bias = b2[co];
        const float* acc = (j == 0) ? acc0 : acc1;
        float ps = 0.f, ps2 = 0.f;
#pragma unroll
        for (int l = 0; l < 15; ++l) {
            float yv = acc[l] + bias;
            if (valid) g_y2[(size_t)(co * 15 + l) * B + b] = yv;
            ps  += yv;
            ps2  = fmaf(yv, yv, ps2);
        }
        if (!valid) { ps = 0.f; ps2 = 0.f; }
#pragma unroll
        for (int off = 16; off; off >>= 1) {
            ps  += __shfl_down_sync(0xffffffffu, ps,  off);
            ps2 += __shfl_down_sync(0xffffffffu, ps2, off);
        }
        if ((tid & 31) == 0) {
            atomicAdd(&g_sum2[co], (double)ps);
            atomicAdd(&g_ssq2[co], (double)ps2);
        }
    }
}

// ---------------------------------------------------------------------------
// Kernel 5: h2 = ELU(BN2(y2)); conv3 (12->6); DFT spectral features
// (f, a, b_off) written to out; phase-head linear v stored + stats.
// (unchanged from R13)
// ---------------------------------------------------------------------------
__global__ void __launch_bounds__(768, 1)
k_conv3(const float* __restrict__ w3, const float* __restrict__ b3,
        const float* __restrict__ pw, const float* __restrict__ pb,
        float* __restrict__ out, int B)
{
    extern __shared__ float sm[];
    float* xs  = sm;                    // 128 * 181
    float* ws  = xs  + 128 * 181;       // 6*12*16 = 1152 (padded)
    float* spw = ws  + 1152;            // 180
    float* ct  = spw + 180;             // 105
    float* st  = ct  + 105;             // 105
    float* sb3 = st  + 105;             // 6
    float* spb = sb3 + 6;               // 12
    float* ssc = spb + 12;              // 12
    float* ssh = ssc + 12;              // 12

    const int tid = threadIdx.x;
    if (tid < 12) { ssc[tid] = g_scale2[tid]; ssh[tid] = g_shift2[tid]; spb[tid] = pb[tid]; }
    if (tid < 6)  sb3[tid] = b3[tid];
    for (int idx = tid; idx < 1080; idx += 768) {
        int r = idx / 15, k = idx - r * 15;
        ws[r * 16 + k] = w3[idx];
    }
    for (int idx = tid; idx < 180;  idx += 768) spw[idx] = pw[idx];
    if (tid < 105) {
        int j = tid / 15 + 1, l = tid - (j - 1) * 15;
        int r = (2 * j * l) % 30;               // exact phase reduction
        float a = (float)r * (1.f / 15.f);
        ct[tid] = cospif(a);
        st[tid] = sinpif(a);
    }
    __syncthreads();

    const int b0 = blockIdx.x * 128;
    for (int idx = tid; idx < 128 * 180; idx += 768) {
        int s2 = idx & 127, i = idx >> 7;
        int bb = b0 + s2;
        float h = 0.f;
        if (bb < B) {
            float yv = g_y2[(size_t)i * B + bb];
            int   co = i / 15;
            float z  = fmaf(yv, ssc[co], ssh[co]);
            h = (z > 0.f) ? z : expm1f(z);
        }
        xs[s2 * 181 + i] = h;
    }
    __syncthreads();

    const int  s     = tid & 127;
    const int  c     = tid >> 7;        // 0..5
    const int  b     = b0 + s;
    const bool valid = (b < B);
    const float* xrow = xs + s * 181;
    const float4* wv4 = reinterpret_cast<const float4*>(ws) + c * 12 * 4;

    float y3[15];
    {
        float bias = sb3[c];
#pragma unroll
        for (int l = 0; l < 15; ++l) y3[l] = bias;
    }

    for (int ci = 0; ci < 12; ++ci) {
        float xv[15];
#pragma unroll
        for (int m = 0; m < 15; ++m) xv[m] = xrow[ci * 15 + m];

        float4 w0 = wv4[ci * 4 + 0];
        float4 w1 = wv4[ci * 4 + 1];
        float4 w2 = wv4[ci * 4 + 2];
        float4 w3v = wv4[ci * 4 + 3];
        float wv[15];
        wv[0]=w0.x; wv[1]=w0.y; wv[2]=w0.z; wv[3]=w0.w;
        wv[4]=w1.x; wv[5]=w1.y; wv[6]=w1.z; wv[7]=w1.w;
        wv[8]=w2.x; wv[9]=w2.y; wv[10]=w2.z; wv[11]=w2.w;
        wv[12]=w3v.x; wv[13]=w3v.y; wv[14]=w3v.z;

#pragma unroll
        for (int m = 0; m < 15; ++m) {
#pragma unroll
            for (int l = 0; l < 15; ++l) {
                int k = m - l + 7;
                if (k >= 0 && k < 15)
                    y3[l] = fmaf(wv[k], xv[m], y3[l]);
            }
        }
    }

    // --- spectral features ---
    float re0 = 0.f;
#pragma unroll
    for (int l = 0; l < 15; ++l) re0 += y3[l];

    float psum = 0.f, fs = 0.f;
#pragma unroll
    for (int j = 1; j <= 7; ++j) {
        float re = 0.f, im = 0.f;
#pragma unroll
        for (int l = 0; l < 15; ++l) {
            re = fmaf(y3[l], ct[(j - 1) * 15 + l], re);
            im = fmaf(y3[l], st[(j - 1) * 15 + l], im);
        }
        float p = re * re + im * im;
        psum += p;
        fs    = fmaf((float)j, p, fs);
    }

    // --- phase head linear ---
    float v0 = spb[c * 2 + 0], v1 = spb[c * 2 + 1];
#pragma unroll
    for (int l = 0; l < 15; ++l) {
        v0 = fmaf(y3[l], spw[(c * 2 + 0) * 15 + l], v0);
        v1 = fmaf(y3[l], spw[(c * 2 + 1) * 15 + l], v1);
    }

    if (valid) {
        out[(size_t)b * 24 + 6 + c]  = fs / psum;
        out[(size_t)b * 24 + 12 + c] = 2.f * sqrtf(psum) * (1.f / 15.f);
        out[(size_t)b * 24 + 18 + c] = re0 * (1.f / 15.f);
        g_v[(size_t)(2 * c + 0) * B + b] = v0;
        g_v[(size_t)(2 * c + 1) * B + b] = v1;
    } else { v0 = 0.f; v1 = 0.f; }

    float s0 = v0, q0 = v0 * v0, s1 = v1, q1 = v1 * v1;
#pragma unroll
    for (int off = 16; off; off >>= 1) {
        s0 += __shfl_down_sync(0xffffffffu, s0, off);
        q0 += __shfl_down_sync(0xffffffffu, q0, off);
        s1 += __shfl_down_sync(0xffffffffu, s1, off);
        q1 += __shfl_down_sync(0xffffffffu, q1, off);
    }
    if ((tid & 31) == 0) {
        atomicAdd(&g_vsum[2 * c + 0], (double)s0);
        atomicAdd(&g_vssq[2 * c + 0], (double)q0);
        atomicAdd(&g_vsum[2 * c + 1], (double)s1);
        atomicAdd(&g_vssq[2 * c + 1], (double)q1);
    }
}

// ---------------------------------------------------------------------------
// Kernel 7: batch-normalize v, phase = atan2(v1, v0) / (2*pi)
// ---------------------------------------------------------------------------
__global__ void k_phase(float* __restrict__ out, int B)
{
    int b = blockIdx.x * blockDim.x + threadIdx.x;
    if (b >= B) return;
    const float inv2pi = 0.15915494309189535f;
#pragma unroll
    for (int c = 0; c < 6; ++c) {
        float v0 = fmaf(g_v[(size_t)(2 * c + 0) * B + b], g_vscale[2 * c + 0], g_vshift[2 * c + 0]);
        float v1 = fmaf(g_v[(size_t)(2 * c + 1) * B + b], g_vscale[2 * c + 1], g_vshift[2 * c + 1]);
        out[(size_t)b * 24 + c] = atan2f(v1, v0) * inv2pi;
    }
}

// ---------------------------------------------------------------------------
extern "C" void kernel_launch(void* const* d_in, const int* in_sizes, int n_in,
                              void* d_out, int out_size)
{
    const float* x   = (const float*)d_in[0];
    const float* w1  = (const float*)d_in[1];
    const float* b1  = (const float*)d_in[2];
    const float* g1  = (const float*)d_in[3];
    const float* be1 = (const float*)d_in[4];
    const float* w2  = (const float*)d_in[5];
    const float* b2  = (const float*)d_in[6];
    const float* g2  = (const float*)d_in[7];
    const float* be2 = (const float*)d_in[8];
    const float* w3  = (const float*)d_in[9];
    const float* b3  = (const float*)d_in[10];
    const float* pw  = (const float*)d_in[11];
    const float* pb  = (const float*)d_in[12];
    const float* pg  = (const float*)d_in[13];
    const float* pbe = (const float*)d_in[14];
    float* out = (float*)d_out;

    const int B = in_sizes[0] / 720;

    const size_t sm1 = (size_t)(64 * 721 + 12 * 48 * 16) * sizeof(float);
    const size_t sm2 = (size_t)(64 * 721 + 12 * 48 * 16 + 96) * sizeof(float);
    const size_t sm3 = (size_t)(128 * 181 + 1152 + 180 + 210 + 6 + 12 + 12 + 12) * sizeof(float);

    cudaFuncSetAttribute(k_conv1, cudaFuncAttributeMaxDynamicSharedMemorySize, (int)sm1);
    cudaFuncSetAttribute(k_conv2, cudaFuncAttributeMaxDynamicSharedMemorySize, (int)sm2);
    cudaFuncSetAttribute(k_conv3, cudaFuncAttributeMaxDynamicSharedMemorySize, (int)sm3);

    const double invNL = 1.0 / ((double)B * 15.0);
    const double invB  = 1.0 / (double)B;

    k_zero<<<1, 64>>>();
    k_conv1<<<(B + 63) / 64, 768, sm1>>>(x, w1, b1, B);
    k_finalize<<<1, 48>>>(g1, be1, 0, 48, invNL);
    k_conv2<<<(B + 63) / 64, 384, sm2>>>(w2, b2, B);
    k_finalize<<<1, 12>>>(g2, be2, 1, 12, invNL);
    k_conv3<<<(B + 127) / 128, 768, sm3>>>(w3, b3, pw, pb, out, B);
    k_finalize<<<1, 12>>>(pg, pbe, 2, 12, invB);
    k_phase<<<(B + 255) / 256, 256>>>(out, B);
}

// round 16
// speedup vs baseline: 1.1436x; 1.1436x over previous
#include <cuda_runtime.h>
#include <math.h>

// ---------------------------------------------------------------------------
// PeriodicEncoder: 3x Conv1d(K=15, same) + train-mode BN + ELU, DFT spectral
// stats, batch-normalized phase head.  B=65536, Cin=48, L=15.
//
// R15: conv2 rebuilt on packed fma.rn.f32x2 (2 fp32 FMA / issue slot):
//  - transposed x-tile xs[i][66] -> sample-pair LDS.64
//  - 768 thr = 32 pairs x 12 co x 2 ci-halves (24 warps/SM kept)
//  - halves combined via smem scratch; float2 coalesced stores
// conv1 / conv3 byte-identical to R13 (best known).
// ---------------------------------------------------------------------------

#define HOR   15
#define CIN1  48
#define COUT1 48
#define COUT2 12
#define LATD  6
#define BMAX  65536

__device__ float  g_y1[(size_t)COUT1 * HOR * BMAX];   // conv1 raw output, [720][B]
__device__ float  g_y2[(size_t)COUT2 * HOR * BMAX];   // conv2 raw output, [180][B]
__device__ float  g_v [(size_t)LATD * 2 * BMAX];      // phase-head pre-BN, [12][B]

__device__ double g_sum1[COUT1], g_ssq1[COUT1];
__device__ double g_sum2[COUT2], g_ssq2[COUT2];
__device__ double g_vsum[LATD * 2], g_vssq[LATD * 2];

__device__ float  g_scale1[COUT1], g_shift1[COUT1];
__device__ float  g_scale2[COUT2], g_shift2[COUT2];
__device__ float  g_vscale[LATD * 2], g_vshift[LATD * 2];

// ---------------------------------------------------------------------------
// packed f32x2 helpers (sm_103a)
// ---------------------------------------------------------------------------
typedef unsigned long long ull;

__device__ __forceinline__ ull packf2(float lo, float hi)
{
    ull r;
    asm("mov.b64 %0, {%1, %2};" : "=l"(r) : "f"(lo), "f"(hi));
    return r;
}
__device__ __forceinline__ void unpackf2(ull v, float& lo, float& hi)
{
    asm("mov.b64 {%0, %1}, %2;" : "=f"(lo), "=f"(hi) : "l"(v));
}
__device__ __forceinline__ ull fma2(ull a, ull b, ull c)
{
    ull d;
    asm("fma.rn.f32x2 %0, %1, %2, %3;" : "=l"(d) : "l"(a), "l"(b), "l"(c));
    return d;
}
__device__ __forceinline__ ull add2(ull a, ull b)
{
    ull d;
    asm("add.rn.f32x2 %0, %1, %2;" : "=l"(d) : "l"(a), "l"(b));
    return d;
}

// ---------------------------------------------------------------------------
__global__ void k_zero()
{
    int t = threadIdx.x;
    if (t < COUT1) { g_sum1[t] = 0.0; g_ssq1[t] = 0.0; }
    if (t < COUT2) {
        g_sum2[t] = 0.0; g_ssq2[t] = 0.0;
        g_vsum[t] = 0.0; g_vssq[t] = 0.0;
    }
}

// ---------------------------------------------------------------------------
// Inner conv micro-kernel (scalar): 48 ci, one co.  (used by conv1)
// ---------------------------------------------------------------------------
__device__ __forceinline__ void conv48(const float* __restrict__ xrow,
                                       const float4* __restrict__ wv4,
                                       float acc[15])
{
    for (int ci = 0; ci < 48; ++ci) {
        float xv[15];
#pragma unroll
        for (int m = 0; m < 15; ++m) xv[m] = xrow[ci * 15 + m];

        float4 w0 = wv4[ci * 4 + 0];
        float4 w1 = wv4[ci * 4 + 1];
        float4 w2 = wv4[ci * 4 + 2];
        float4 w3 = wv4[ci * 4 + 3];
        float wv[15];
        wv[0]=w0.x; wv[1]=w0.y; wv[2]=w0.z; wv[3]=w0.w;
        wv[4]=w1.x; wv[5]=w1.y; wv[6]=w1.z; wv[7]=w1.w;
        wv[8]=w2.x; wv[9]=w2.y; wv[10]=w2.z; wv[11]=w2.w;
        wv[12]=w3.x; wv[13]=w3.y; wv[14]=w3.z;

#pragma unroll
        for (int m = 0; m < 15; ++m) {
#pragma unroll
            for (int l = 0; l < 15; ++l) {
                int k = m - l + 7;
                if (k >= 0 && k < 15)
                    acc[l] = fmaf(wv[k], xv[m], acc[l]);
            }
        }
    }
}

// ---------------------------------------------------------------------------
// Kernel 1: conv1 (48->48, K=15) + BN1 statistics.  (unchanged from R13)
// ---------------------------------------------------------------------------
__global__ void __launch_bounds__(768, 1)
k_conv1(const float* __restrict__ x, const float* __restrict__ w1,
        const float* __restrict__ b1, int B)
{
    extern __shared__ float sm[];
    float* xs = sm;                 // 64 * 721
    float* ws = sm + 64 * 721;      // 12 * 48 * 16

    const int tid = threadIdx.x;
    const int s   = tid & 63;
    const int cg  = tid >> 6;
    const int b0  = blockIdx.x * 64;

    for (int idx = tid; idx < 64 * 720; idx += 768) {
        int ss = idx / 720, i = idx - ss * 720;
        int b  = b0 + ss;
        xs[ss * 721 + i] = (b < B) ? x[(size_t)b * 720 + i] : 0.f;
    }

    const int  b     = b0 + s;
    const bool valid = (b < B);
    const float* xrow = xs + s * 721;
    const float4* wv4 = reinterpret_cast<const float4*>(ws) + cg * 48 * 4;

    for (int chunk = 0; chunk < 4; ++chunk) {
        __syncthreads();
        const float* wsrc = w1 + (size_t)chunk * 12 * 720;
        for (int idx = tid; idx < 12 * 720; idx += 768) {
            int r = idx / 15, k = idx - r * 15;
            ws[r * 16 + k] = wsrc[idx];
        }
        __syncthreads();

        float acc[15];
#pragma unroll
        for (int l = 0; l < 15; ++l) acc[l] = 0.f;

        conv48(xrow, wv4, acc);

        const int   co   = chunk * 12 + cg;
        const float bias = b1[co];
        float ps = 0.f, ps2 = 0.f;
#pragma unroll
        for (int l = 0; l < 15; ++l) {
            float yv = acc[l] + bias;
            if (valid) g_y1[(size_t)(co * 15 + l) * B + b] = yv;
            ps  += yv;
            ps2  = fmaf(yv, yv, ps2);
        }
        if (!valid) { ps = 0.f; ps2 = 0.f; }
#pragma unroll
        for (int off = 16; off; off >>= 1) {
            ps  += __shfl_down_sync(0xffffffffu, ps,  off);
            ps2 += __shfl_down_sync(0xffffffffu, ps2, off);
        }
        if ((tid & 31) == 0) {
            atomicAdd(&g_sum1[co], (double)ps);
            atomicAdd(&g_ssq1[co], (double)ps2);
        }
    }
}

// ---------------------------------------------------------------------------
// BN finalize
// ---------------------------------------------------------------------------
__global__ void k_finalize(const float* __restrict__ g,
                           const float* __restrict__ bb,
                           int which, int C, double invN)
{
    int c = threadIdx.x;
    if (c >= C) return;
    double su, sq; float* sc; float* sh;
    if (which == 0)      { su = g_sum1[c]; sq = g_ssq1[c]; sc = g_scale1; sh = g_shift1; }
    else if (which == 1) { su = g_sum2[c]; sq = g_ssq2[c]; sc = g_scale2; sh = g_shift2; }
    else                 { su = g_vsum[c]; sq = g_vssq[c]; sc = g_vscale; sh = g_vshift; }
    double m   = su * invN;
    double var = sq * invN - m * m;
    double rs  = 1.0 / sqrt(var + 1e-5);
    double scl = (double)g[c] * rs;
    sc[c] = (float)scl;
    sh[c] = (float)((double)bb[c] - m * scl);
}

// ---------------------------------------------------------------------------
// Kernel 3: h1 = ELU(BN1(y1)); conv2 (48->12) + BN2 statistics.
// R15: packed f32x2. 768 thr = 32 sample-pairs x 12 co x 2 ci-halves.
// xs transposed [i][66]: pair (2p,2p+1) loads x as one aligned LDS.64.
// smem: 720*66 + 12*48*16 + 96 = 56832 floats = 227,328 B.
// ---------------------------------------------------------------------------
__global__ void __launch_bounds__(768, 1)
k_conv2(const float* __restrict__ w2, const float* __restrict__ b2, int B)
{
    extern __shared__ float sm[];
    float* xs  = sm;                   // 720 * 66 (transposed, padded)
    float* ws  = sm + 720 * 66;        // 12 * 48 * 16 (padded)
    float* ssc = ws + 12 * 48 * 16;    // 48
    float* ssh = ssc + 48;             // 48

    const int tid = threadIdx.x;
    if (tid < 48) { ssc[tid] = g_scale1[tid]; ssh[tid] = g_shift1[tid]; }
    for (int idx = tid; idx < 12 * 720; idx += 768) {
        int r = idx / 15, k = idx - r * 15;
        ws[r * 16 + k] = w2[idx];
    }
    __syncthreads();

    const int b0 = blockIdx.x * 64;
    // load + ELU into transposed tile: xs[i*66 + s]
    for (int idx = tid; idx < 64 * 720; idx += 768) {
        int s2 = idx & 63, i = idx >> 6;
        int bb = b0 + s2;
        float h = 0.f;
        if (bb < B) {
            float yv = g_y1[(size_t)i * B + bb];
            int   co = i / 15;
            float z  = fmaf(yv, ssc[co], ssh[co]);
            h = (z > 0.f) ? z : expm1f(z);
        }
        xs[i * 66 + s2] = h;
    }
    __syncthreads();

    const int p  = tid & 31;           // sample pair 0..31
    const int c  = (tid >> 5) % 12;    // output channel
    const int h  = tid / 384;          // ci half 0/1
    const int ci0 = h * 24;

    const ull* xq = reinterpret_cast<const ull*>(xs);   // index = 33*i + p
    const float4* wv4 = reinterpret_cast<const float4*>(ws) + c * 48 * 4;

    ull acc2[15];
#pragma unroll
    for (int l = 0; l < 15; ++l) acc2[l] = 0ull;

    for (int ci = 0; ci < 24; ++ci) {
        const int cci = ci0 + ci;
        const ull* xrow = xq + (cci * 15) * 33 + p;

        // weights for this ci, duplicated into both f32x2 halves
        ull wd[15];
        {
            float4 t0 = wv4[cci * 4 + 0];
            wd[0] = packf2(t0.x, t0.x); wd[1] = packf2(t0.y, t0.y);
            wd[2] = packf2(t0.z, t0.z); wd[3] = packf2(t0.w, t0.w);
            float4 t1 = wv4[cci * 4 + 1];
            wd[4] = packf2(t1.x, t1.x); wd[5] = packf2(t1.y, t1.y);
            wd[6] = packf2(t1.z, t1.z); wd[7] = packf2(t1.w, t1.w);
            float4 t2 = wv4[cci * 4 + 2];
            wd[8]  = packf2(t2.x, t2.x); wd[9]  = packf2(t2.y, t2.y);
            wd[10] = packf2(t2.z, t2.z); wd[11] = packf2(t2.w, t2.w);
            float4 t3 = wv4[cci * 4 + 3];
            wd[12] = packf2(t3.x, t3.x); wd[13] = packf2(t3.y, t3.y);
            wd[14] = packf2(t3.z, t3.z);
        }

#pragma unroll
        for (int m = 0; m < 15; ++m) {
            ull xv2 = xrow[m * 33];
#pragma unroll
            for (int l = 0; l < 15; ++l) {
                int k = m - l + 7;
                if (k >= 0 && k < 15)
                    acc2[l] = fma2(wd[k], xv2, acc2[l]);
            }
        }
    }

    // combine ci-halves via smem scratch (reuses xs region)
    __syncthreads();
    ull* scratch = reinterpret_cast<ull*>(xs);
    const int slot = (c * 32 + p) * 15;
    if (h == 1) {
#pragma unroll
        for (int l = 0; l < 15; ++l) scratch[slot + l] = acc2[l];
    }
    __syncthreads();

    if (h == 0) {
#pragma unroll
        for (int l = 0; l < 15; ++l) acc2[l] = add2(acc2[l], scratch[slot + l]);

        const int  b      = b0 + 2 * p;
        const bool valid0 = (b < B);
        const bool valid1 = (b + 1 < B);
        const float bias  = b2[c];

        float ps = 0.f, ps2 = 0.f;
#pragma unroll
        for (int l = 0; l < 15; ++l) {
            float lo, hi;
            unpackf2(acc2[l], lo, hi);
            float y0 = lo + bias;
            float y1 = hi + bias;
            const size_t row = (size_t)(c * 15 + l) * B;
            if (valid1) {
                float2 st; st.x = y0; st.y = y1;
                *reinterpret_cast<float2*>(&g_y2[row + b]) = st;
            } else if (valid0) {
                g_y2[row + b] = y0;
            }
            float e0 = valid0 ? y0 : 0.f;
            float e1 = valid1 ? y1 : 0.f;
            ps  += e0 + e1;
            ps2  = fmaf(e0, e0, ps2);
            ps2  = fmaf(e1, e1, ps2);
        }

#pragma unroll
        for (int off = 16; off; off >>= 1) {
            ps  += __shfl_down_sync(0xffffffffu, ps,  off);
            ps2 += __shfl_down_sync(0xffffffffu, ps2, off);
        }
        if (p == 0) {
            atomicAdd(&g_sum2[c], (double)ps);
            atomicAdd(&g_ssq2[c], (double)ps2);
        }
    }
}

// ---------------------------------------------------------------------------
// Kernel 5: h2 = ELU(BN2(y2)); conv3 (12->6) + features. (unchanged from R13)
// ---------------------------------------------------------------------------
__global__ void __launch_bounds__(768, 1)
k_conv3(const float* __restrict__ w3, const float* __restrict__ b3,
        const float* __restrict__ pw, const float* __restrict__ pb,
        float* __restrict__ out, int B)
{
    extern __shared__ float sm[];
    float* xs  = sm;                    // 128 * 181
    float* ws  = xs  + 128 * 181;       // 1152
    float* spw = ws  + 1152;            // 180
    float* ct  = spw + 180;             // 105
    float* st  = ct  + 105;             // 105
    float* sb3 = st  + 105;             // 6
    float* spb = sb3 + 6;               // 12
    float* ssc = spb + 12;              // 12
    float* ssh = ssc + 12;              // 12

    const int tid = threadIdx.x;
    if (tid < 12) { ssc[tid] = g_scale2[tid]; ssh[tid] = g_shift2[tid]; spb[tid] = pb[tid]; }
    if (tid < 6)  sb3[tid] = b3[tid];
    for (int idx = tid; idx < 1080; idx += 768) {
        int r = idx / 15, k = idx - r * 15;
        ws[r * 16 + k] = w3[idx];
    }
    for (int idx = tid; idx < 180;  idx += 768) spw[idx] = pw[idx];
    if (tid < 105) {
        int j = tid / 15 + 1, l = tid - (j - 1) * 15;
        int r = (2 * j * l) % 30;
        float a = (float)r * (1.f / 15.f);
        ct[tid] = cospif(a);
        st[tid] = sinpif(a);
    }
    __syncthreads();

    const int b0 = blockIdx.x * 128;
    for (int idx = tid; idx < 128 * 180; idx += 768) {
        int s2 = idx & 127, i = idx >> 7;
        int bb = b0 + s2;
        float h = 0.f;
        if (bb < B) {
            float yv = g_y2[(size_t)i * B + bb];
            int   co = i / 15;
            float z  = fmaf(yv, ssc[co], ssh[co]);
            h = (z > 0.f) ? z : expm1f(z);
        }
        xs[s2 * 181 + i] = h;
    }
    __syncthreads();

    const int  s     = tid & 127;
    const int  c     = tid >> 7;
    const int  b     = b0 + s;
    const bool valid = (b < B);
    const float* xrow = xs + s * 181;
    const float4* wv4 = reinterpret_cast<const float4*>(ws) + c * 12 * 4;

    float y3[15];
    {
        float bias = sb3[c];
#pragma unroll
        for (int l = 0; l < 15; ++l) y3[l] = bias;
    }

    for (int ci = 0; ci < 12; ++ci) {
        float xv[15];
#pragma unroll
        for (int m = 0; m < 15; ++m) xv[m] = xrow[ci * 15 + m];

        float4 w0 = wv4[ci * 4 + 0];
        float4 w1 = wv4[ci * 4 + 1];
        float4 w2 = wv4[ci * 4 + 2];
        float4 w3v = wv4[ci * 4 + 3];
        float wv[15];
        wv[0]=w0.x; wv[1]=w0.y; wv[2]=w0.z; wv[3]=w0.w;
        wv[4]=w1.x; wv[5]=w1.y; wv[6]=w1.z; wv[7]=w1.w;
        wv[8]=w2.x; wv[9]=w2.y; wv[10]=w2.z; wv[11]=w2.w;
        wv[12]=w3v.x; wv[13]=w3v.y; wv[14]=w3v.z;

#pragma unroll
        for (int m = 0; m < 15; ++m) {
#pragma unroll
            for (int l = 0; l < 15; ++l) {
                int k = m - l + 7;
                if (k >= 0 && k < 15)
                    y3[l] = fmaf(wv[k], xv[m], y3[l]);
            }
        }
    }

    float re0 = 0.f;
#pragma unroll
    for (int l = 0; l < 15; ++l) re0 += y3[l];

    float psum = 0.f, fs = 0.f;
#pragma unroll
    for (int j = 1; j <= 7; ++j) {
        float re = 0.f, im = 0.f;
#pragma unroll
        for (int l = 0; l < 15; ++l) {
            re = fmaf(y3[l], ct[(j - 1) * 15 + l], re);
            im = fmaf(y3[l], st[(j - 1) * 15 + l], im);
        }
        float pp = re * re + im * im;
        psum += pp;
        fs    = fmaf((float)j, pp, fs);
    }

    float v0 = spb[c * 2 + 0], v1 = spb[c * 2 + 1];
#pragma unroll
    for (int l = 0; l < 15; ++l) {
        v0 = fmaf(y3[l], spw[(c * 2 + 0) * 15 + l], v0);
        v1 = fmaf(y3[l], spw[(c * 2 + 1) * 15 + l], v1);
    }

    if (valid) {
        out[(size_t)b * 24 + 6 + c]  = fs / psum;
        out[(size_t)b * 24 + 12 + c] = 2.f * sqrtf(psum) * (1.f / 15.f);
        out[(size_t)b * 24 + 18 + c] = re0 * (1.f / 15.f);
        g_v[(size_t)(2 * c + 0) * B + b] = v0;
        g_v[(size_t)(2 * c + 1) * B + b] = v1;
    } else { v0 = 0.f; v1 = 0.f; }

    float s0 = v0, q0 = v0 * v0, s1 = v1, q1 = v1 * v1;
#pragma unroll
    for (int off = 16; off; off >>= 1) {
        s0 += __shfl_down_sync(0xffffffffu, s0, off);
        q0 += __shfl_down_sync(0xffffffffu, q0, off);
        s1 += __shfl_down_sync(0xffffffffu, s1, off);
        q1 += __shfl_down_sync(0xffffffffu, q1, off);
    }
    if ((tid & 31) == 0) {
        atomicAdd(&g_vsum[2 * c + 0], (double)s0);
        atomicAdd(&g_vssq[2 * c + 0], (double)q0);
        atomicAdd(&g_vsum[2 * c + 1], (double)s1);
        atomicAdd(&g_vssq[2 * c + 1], (double)q1);
    }
}

// ---------------------------------------------------------------------------
// Kernel 7: batch-normalize v, phase = atan2(v1, v0) / (2*pi)
// ---------------------------------------------------------------------------
__global__ void k_phase(float* __restrict__ out, int B)
{
    int b = blockIdx.x * blockDim.x + threadIdx.x;
    if (b >= B) return;
    const float inv2pi = 0.15915494309189535f;
#pragma unroll
    for (int c = 0; c < 6; ++c) {
        float v0 = fmaf(g_v[(size_t)(2 * c + 0) * B + b], g_vscale[2 * c + 0], g_vshift[2 * c + 0]);
        float v1 = fmaf(g_v[(size_t)(2 * c + 1) * B + b], g_vscale[2 * c + 1], g_vshift[2 * c + 1]);
        out[(size_t)b * 24 + c] = atan2f(v1, v0) * inv2pi;
    }
}

// ---------------------------------------------------------------------------
extern "C" void kernel_launch(void* const* d_in, const int* in_sizes, int n_in,
                              void* d_out, int out_size)
{
    const float* x   = (const float*)d_in[0];
    const float* w1  = (const float*)d_in[1];
    const float* b1  = (const float*)d_in[2];
    const float* g1  = (const float*)d_in[3];
    const float* be1 = (const float*)d_in[4];
    const float* w2  = (const float*)d_in[5];
    const float* b2  = (const float*)d_in[6];
    const float* g2  = (const float*)d_in[7];
    const float* be2 = (const float*)d_in[8];
    const float* w3  = (const float*)d_in[9];
    const float* b3  = (const float*)d_in[10];
    const float* pw  = (const float*)d_in[11];
    const float* pb  = (const float*)d_in[12];
    const float* pg  = (const float*)d_in[13];
    const float* pbe = (const float*)d_in[14];
    float* out = (float*)d_out;

    const int B = in_sizes[0] / 720;

    const size_t sm1 = (size_t)(64 * 721 + 12 * 48 * 16) * sizeof(float);
    const size_t sm2 = (size_t)(720 * 66 + 12 * 48 * 16 + 96) * sizeof(float);
    const size_t sm3 = (size_t)(128 * 181 + 1152 + 180 + 210 + 6 + 12 + 12 + 12) * sizeof(float);

    cudaFuncSetAttribute(k_conv1, cudaFuncAttributeMaxDynamicSharedMemorySize, (int)sm1);
    cudaFuncSetAttribute(k_conv2, cudaFuncAttributeMaxDynamicSharedMemorySize, (int)sm2);
    cudaFuncSetAttribute(k_conv3, cudaFuncAttributeMaxDynamicSharedMemorySize, (int)sm3);

    const double invNL = 1.0 / ((double)B * 15.0);
    const double invB  = 1.0 / (double)B;

    k_zero<<<1, 64>>>();
    k_conv1<<<(B + 63) / 64, 768, sm1>>>(x, w1, b1, B);
    k_finalize<<<1, 48>>>(g1, be1, 0, 48, invNL);
    k_conv2<<<(B + 63) / 64, 768, sm2>>>(w2, b2, B);
    k_finalize<<<1, 12>>>(g2, be2, 1, 12, invNL);
    k_conv3<<<(B + 127) / 128, 768, sm3>>>(w3, b3, pw, pb, out, B);
    k_finalize<<<1, 12>>>(pg, pbe, 2, 12, invB);
    k_phase<<<(B + 255) / 256, 256>>>(out, B);
}

// round 17
// speedup vs baseline: 1.1901x; 1.0407x over previous
#include <cuda_runtime.h>
#include <math.h>

// ---------------------------------------------------------------------------
// PeriodicEncoder: 3x Conv1d(K=15, same) + train-mode BN + ELU, DFT spectral
// stats, batch-normalized phase head.  B=65536, Cin=48, L=15.
//
// R16: conv1 ported to packed fma.rn.f32x2:
//  - transposed x-tile xs[i][66] -> sample-pair LDS.64 (loaded i-major so
//    gmem reads stay coalesced)
//  - 768 thr = 24 warps; warp = (co, pair-block); lanes 0-15/16-31 = ci-halves
//  - halves merged intra-warp via shfl_xor(16); no smem scratch, no extra sync
// conv2 (R15 f32x2) / conv3 (R13) byte-identical.
// ---------------------------------------------------------------------------

#define HOR   15
#define CIN1  48
#define COUT1 48
#define COUT2 12
#define LATD  6
#define BMAX  65536

__device__ float  g_y1[(size_t)COUT1 * HOR * BMAX];   // conv1 raw output, [720][B]
__device__ float  g_y2[(size_t)COUT2 * HOR * BMAX];   // conv2 raw output, [180][B]
__device__ float  g_v [(size_t)LATD * 2 * BMAX];      // phase-head pre-BN, [12][B]

__device__ double g_sum1[COUT1], g_ssq1[COUT1];
__device__ double g_sum2[COUT2], g_ssq2[COUT2];
__device__ double g_vsum[LATD * 2], g_vssq[LATD * 2];

__device__ float  g_scale1[COUT1], g_shift1[COUT1];
__device__ float  g_scale2[COUT2], g_shift2[COUT2];
__device__ float  g_vscale[LATD * 2], g_vshift[LATD * 2];

// ---------------------------------------------------------------------------
// packed f32x2 helpers (sm_103a)
// ---------------------------------------------------------------------------
typedef unsigned long long ull;

__device__ __forceinline__ ull packf2(float lo, float hi)
{
    ull r;
    asm("mov.b64 %0, {%1, %2};" : "=l"(r) : "f"(lo), "f"(hi));
    return r;
}
__device__ __forceinline__ void unpackf2(ull v, float& lo, float& hi)
{
    asm("mov.b64 {%0, %1}, %2;" : "=f"(lo), "=f"(hi) : "l"(v));
}
__device__ __forceinline__ ull fma2(ull a, ull b, ull c)
{
    ull d;
    asm("fma.rn.f32x2 %0, %1, %2, %3;" : "=l"(d) : "l"(a), "l"(b), "l"(c));
    return d;
}
__device__ __forceinline__ ull add2(ull a, ull b)
{
    ull d;
    asm("add.rn.f32x2 %0, %1, %2;" : "=l"(d) : "l"(a), "l"(b));
    return d;
}

// ---------------------------------------------------------------------------
__global__ void k_zero()
{
    int t = threadIdx.x;
    if (t < COUT1) { g_sum1[t] = 0.0; g_ssq1[t] = 0.0; }
    if (t < COUT2) {
        g_sum2[t] = 0.0; g_ssq2[t] = 0.0;
        g_vsum[t] = 0.0; g_vssq[t] = 0.0;
    }
}

// ---------------------------------------------------------------------------
// f32x2 inner loop: 24 input channels starting at ci0, one co.
// xq: transposed tile base (ull view, row stride 33), p: sample pair.
// ---------------------------------------------------------------------------
__device__ __forceinline__ void conv24_f2(const ull* __restrict__ xq,
                                          const float4* __restrict__ wv4,
                                          int ci0, int p, ull acc2[15])
{
    for (int ci = 0; ci < 24; ++ci) {
        const int cci = ci0 + ci;
        const ull* xrow = xq + (cci * 15) * 33 + p;

        ull wd[15];
        {
            float4 t0 = wv4[cci * 4 + 0];
            wd[0] = packf2(t0.x, t0.x); wd[1] = packf2(t0.y, t0.y);
            wd[2] = packf2(t0.z, t0.z); wd[3] = packf2(t0.w, t0.w);
            float4 t1 = wv4[cci * 4 + 1];
            wd[4] = packf2(t1.x, t1.x); wd[5] = packf2(t1.y, t1.y);
            wd[6] = packf2(t1.z, t1.z); wd[7] = packf2(t1.w, t1.w);
            float4 t2 = wv4[cci * 4 + 2];
            wd[8]  = packf2(t2.x, t2.x); wd[9]  = packf2(t2.y, t2.y);
            wd[10] = packf2(t2.z, t2.z); wd[11] = packf2(t2.w, t2.w);
            float4 t3 = wv4[cci * 4 + 3];
            wd[12] = packf2(t3.x, t3.x); wd[13] = packf2(t3.y, t3.y);
            wd[14] = packf2(t3.z, t3.z);
        }

#pragma unroll
        for (int m = 0; m < 15; ++m) {
            ull xv2 = xrow[m * 33];
#pragma unroll
            for (int l = 0; l < 15; ++l) {
                int k = m - l + 7;
                if (k >= 0 && k < 15)
                    acc2[l] = fma2(wd[k], xv2, acc2[l]);
            }
        }
    }
}

// ---------------------------------------------------------------------------
// Kernel 1: conv1 (48->48, K=15) + BN1 statistics.  (R16: f32x2)
// 768 thr = 24 warps; warp w: co = w%12, pair-block = w/12 (16 pairs each);
// lane: pl = lane&15 (pair within block), h = lane>>4 (ci half).
// smem: x 720*66 (190.1KB) + w 12*48*16 (36.9KB) = 226.9KB -> 24 warps/SM.
// ---------------------------------------------------------------------------
__global__ void __launch_bounds__(768, 1)
k_conv1(const float* __restrict__ x, const float* __restrict__ w1,
        const float* __restrict__ b1, int B)
{
    extern __shared__ float sm[];
    float* xs = sm;                 // 720 * 66 (transposed, padded)
    float* ws = sm + 720 * 66;      // 12 * 48 * 16 (padded)

    const int tid = threadIdx.x;
    const int b0  = blockIdx.x * 64;

    // load x transposed, i-major so gmem stays coalesced
    for (int idx = tid; idx < 64 * 720; idx += 768) {
        int i = idx % 720, s2 = idx / 720;
        int bb = b0 + s2;
        xs[i * 66 + s2] = (bb < B) ? x[(size_t)bb * 720 + i] : 0.f;
    }

    const int lane = tid & 31;
    const int w    = tid >> 5;         // 0..23
    const int co_g = w % 12;           // co within chunk
    const int pb   = w / 12;           // pair block 0/1
    const int pl   = lane & 15;
    const int h    = lane >> 4;        // ci half
    const int p    = pb * 16 + pl;     // pair 0..31
    const int ci0  = h * 24;

    const ull* xq = reinterpret_cast<const ull*>(xs);
    const float4* wv4 = reinterpret_cast<const float4*>(ws) + co_g * 48 * 4;

    const int  b      = b0 + 2 * p;
    const bool valid0 = (b < B);
    const bool valid1 = (b + 1 < B);

    for (int chunk = 0; chunk < 4; ++chunk) {
        __syncthreads();
        const float* wsrc = w1 + (size_t)chunk * 12 * 720;
        for (int idx = tid; idx < 12 * 720; idx += 768) {
            int r = idx / 15, k = idx - r * 15;
            ws[r * 16 + k] = wsrc[idx];
        }
        __syncthreads();

        ull acc2[15];
#pragma unroll
        for (int l = 0; l < 15; ++l) acc2[l] = 0ull;

        conv24_f2(xq, wv4, ci0, p, acc2);

        // merge ci halves within the warp
#pragma unroll
        for (int l = 0; l < 15; ++l) {
            ull o = __shfl_xor_sync(0xffffffffu, acc2[l], 16);
            acc2[l] = add2(acc2[l], o);
        }

        const int   co   = chunk * 12 + co_g;
        const float bias = b1[co];
        float ps = 0.f, ps2 = 0.f;
#pragma unroll
        for (int l = 0; l < 15; ++l) {
            float lo, hi;
            unpackf2(acc2[l], lo, hi);
            float y0 = lo + bias;
            float y1 = hi + bias;
            if (h == 0) {
                const size_t row = (size_t)(co * 15 + l) * B;
                if (valid1) {
                    float2 st; st.x = y0; st.y = y1;
                    *reinterpret_cast<float2*>(&g_y1[row + b]) = st;
                } else if (valid0) {
                    g_y1[row + b] = y0;
                }
                float e0 = valid0 ? y0 : 0.f;
                float e1 = valid1 ? y1 : 0.f;
                ps  += e0 + e1;
                ps2  = fmaf(e0, e0, ps2);
                ps2  = fmaf(e1, e1, ps2);
            }
        }

#pragma unroll
        for (int off = 16; off; off >>= 1) {
            ps  += __shfl_down_sync(0xffffffffu, ps,  off);
            ps2 += __shfl_down_sync(0xffffffffu, ps2, off);
        }
        if (lane == 0) {
            atomicAdd(&g_sum1[co], (double)ps);
            atomicAdd(&g_ssq1[co], (double)ps2);
        }
    }
}

// ---------------------------------------------------------------------------
// BN finalize
// ---------------------------------------------------------------------------
__global__ void k_finalize(const float* __restrict__ g,
                           const float* __restrict__ bb,
                           int which, int C, double invN)
{
    int c = threadIdx.x;
    if (c >= C) return;
    double su, sq; float* sc; float* sh;
    if (which == 0)      { su = g_sum1[c]; sq = g_ssq1[c]; sc = g_scale1; sh = g_shift1; }
    else if (which == 1) { su = g_sum2[c]; sq = g_ssq2[c]; sc = g_scale2; sh = g_shift2; }
    else                 { su = g_vsum[c]; sq = g_vssq[c]; sc = g_vscale; sh = g_vshift; }
    double m   = su * invN;
    double var = sq * invN - m * m;
    double rs  = 1.0 / sqrt(var + 1e-5);
    double scl = (double)g[c] * rs;
    sc[c] = (float)scl;
    sh[c] = (float)((double)bb[c] - m * scl);
}

// ---------------------------------------------------------------------------
// Kernel 3: h1 = ELU(BN1(y1)); conv2 (48->12) + BN2 statistics.
// (unchanged from R15: f32x2, smem-scratch half combine)
// ---------------------------------------------------------------------------
__global__ void __launch_bounds__(768, 1)
k_conv2(const float* __restrict__ w2, const float* __restrict__ b2, int B)
{
    extern __shared__ float sm[];
    float* xs  = sm;                   // 720 * 66 (transposed, padded)
    float* ws  = sm + 720 * 66;        // 12 * 48 * 16 (padded)
    float* ssc = ws + 12 * 48 * 16;    // 48
    float* ssh = ssc + 48;             // 48

    const int tid = threadIdx.x;
    if (tid < 48) { ssc[tid] = g_scale1[tid]; ssh[tid] = g_shift1[tid]; }
    for (int idx = tid; idx < 12 * 720; idx += 768) {
        int r = idx / 15, k = idx - r * 15;
        ws[r * 16 + k] = w2[idx];
    }
    __syncthreads();

    const int b0 = blockIdx.x * 64;
    for (int idx = tid; idx < 64 * 720; idx += 768) {
        int s2 = idx & 63, i = idx >> 6;
        int bb = b0 + s2;
        float h = 0.f;
        if (bb < B) {
            float yv = g_y1[(size_t)i * B + bb];
            int   co = i / 15;
            float z  = fmaf(yv, ssc[co], ssh[co]);
            h = (z > 0.f) ? z : expm1f(z);
        }
        xs[i * 66 + s2] = h;
    }
    __syncthreads();

    const int p  = tid & 31;           // sample pair 0..31
    const int c  = (tid >> 5) % 12;    // output channel
    const int h  = tid / 384;          // ci half 0/1
    const int ci0 = h * 24;

    const ull* xq = reinterpret_cast<const ull*>(xs);
    const float4* wv4 = reinterpret_cast<const float4*>(ws) + c * 48 * 4;

    ull acc2[15];
#pragma unroll
    for (int l = 0; l < 15; ++l) acc2[l] = 0ull;

    conv24_f2(xq, wv4, ci0, p, acc2);

    // combine ci-halves via smem scratch (reuses xs region)
    __syncthreads();
    ull* scratch = reinterpret_cast<ull*>(xs);
    const int slot = (c * 32 + p) * 15;
    if (h == 1) {
#pragma unroll
        for (int l = 0; l < 15; ++l) scratch[slot + l] = acc2[l];
    }
    __syncthreads();

    if (h == 0) {
#pragma unroll
        for (int l = 0; l < 15; ++l) acc2[l] = add2(acc2[l], scratch[slot + l]);

        const int  b      = b0 + 2 * p;
        const bool valid0 = (b < B);
        const bool valid1 = (b + 1 < B);
        const float bias  = b2[c];

        float ps = 0.f, ps2 = 0.f;
#pragma unroll
        for (int l = 0; l < 15; ++l) {
            float lo, hi;
            unpackf2(acc2[l], lo, hi);
            float y0 = lo + bias;
            float y1 = hi + bias;
            const size_t row = (size_t)(c * 15 + l) * B;
            if (valid1) {
                float2 st; st.x = y0; st.y = y1;
                *reinterpret_cast<float2*>(&g_y2[row + b]) = st;
            } else if (valid0) {
                g_y2[row + b] = y0;
            }
            float e0 = valid0 ? y0 : 0.f;
            float e1 = valid1 ? y1 : 0.f;
            ps  += e0 + e1;
            ps2  = fmaf(e0, e0, ps2);
            ps2  = fmaf(e1, e1, ps2);
        }

#pragma unroll
        for (int off = 16; off; off >>= 1) {
            ps  += __shfl_down_sync(0xffffffffu, ps,  off);
            ps2 += __shfl_down_sync(0xffffffffu, ps2, off);
        }
        if (p == 0) {
            atomicAdd(&g_sum2[c], (double)ps);
            atomicAdd(&g_ssq2[c], (double)ps2);
        }
    }
}

// ---------------------------------------------------------------------------
// Kernel 5: h2 = ELU(BN2(y2)); conv3 (12->6) + features. (unchanged from R13)
// ---------------------------------------------------------------------------
__global__ void __launch_bounds__(768, 1)
k_conv3(const float* __restrict__ w3, const float* __restrict__ b3,
        const float* __restrict__ pw, const float* __restrict__ pb,
        float* __restrict__ out, int B)
{
    extern __shared__ float sm[];
    float* xs  = sm;                    // 128 * 181
    float* ws  = xs  + 128 * 181;       // 1152
    float* spw = ws  + 1152;            // 180
    float* ct  = spw + 180;             // 105
    float* st  = ct  + 105;             // 105
    float* sb3 = st  + 105;             // 6
    float* spb = sb3 + 6;               // 12
    float* ssc = spb + 12;              // 12
    float* ssh = ssc + 12;              // 12

    const int tid = threadIdx.x;
    if (tid < 12) { ssc[tid] = g_scale2[tid]; ssh[tid] = g_shift2[tid]; spb[tid] = pb[tid]; }
    if (tid < 6)  sb3[tid] = b3[tid];
    for (int idx = tid; idx < 1080; idx += 768) {
        int r = idx / 15, k = idx - r * 15;
        ws[r * 16 + k] = w3[idx];
    }
    for (int idx = tid; idx < 180;  idx += 768) spw[idx] = pw[idx];
    if (tid < 105) {
        int j = tid / 15 + 1, l = tid - (j - 1) * 15;
        int r = (2 * j * l) % 30;
        float a = (float)r * (1.f / 15.f);
        ct[tid] = cospif(a);
        st[tid] = sinpif(a);
    }
    __syncthreads();

    const int b0 = blockIdx.x * 128;
    for (int idx = tid; idx < 128 * 180; idx += 768) {
        int s2 = idx & 127, i = idx >> 7;
        int bb = b0 + s2;
        float h = 0.f;
        if (bb < B) {
            float yv = g_y2[(size_t)i * B + bb];
            int   co = i / 15;
            float z  = fmaf(yv, ssc[co], ssh[co]);
            h = (z > 0.f) ? z : expm1f(z);
        }
        xs[s2 * 181 + i] = h;
    }
    __syncthreads();

    const int  s     = tid & 127;
    const int  c     = tid >> 7;
    const int  b     = b0 + s;
    const bool valid = (b < B);
    const float* xrow = xs + s * 181;
    const float4* wv4 = reinterpret_cast<const float4*>(ws) + c * 12 * 4;

    float y3[15];
    {
        float bias = sb3[c];
#pragma unroll
        for (int l = 0; l < 15; ++l) y3[l] = bias;
    }

    for (int ci = 0; ci < 12; ++ci) {
        float xv[15];
#pragma unroll
        for (int m = 0; m < 15; ++m) xv[m] = xrow[ci * 15 + m];

        float4 w0 = wv4[ci * 4 + 0];
        float4 w1 = wv4[ci * 4 + 1];
        float4 w2 = wv4[ci * 4 + 2];
        float4 w3v = wv4[ci * 4 + 3];
        float wv[15];
        wv[0]=w0.x; wv[1]=w0.y; wv[2]=w0.z; wv[3]=w0.w;
        wv[4]=w1.x; wv[5]=w1.y; wv[6]=w1.z; wv[7]=w1.w;
        wv[8]=w2.x; wv[9]=w2.y; wv[10]=w2.z; wv[11]=w2.w;
        wv[12]=w3v.x; wv[13]=w3v.y; wv[14]=w3v.z;

#pragma unroll
        for (int m = 0; m < 15; ++m) {
#pragma unroll
            for (int l = 0; l < 15; ++l) {
                int k = m - l + 7;
                if (k >= 0 && k < 15)
                    y3[l] = fmaf(wv[k], xv[m], y3[l]);
            }
        }
    }

    float re0 = 0.f;
#pragma unroll
    for (int l = 0; l < 15; ++l) re0 += y3[l];

    float psum = 0.f, fs = 0.f;
#pragma unroll
    for (int j = 1; j <= 7; ++j) {
        float re = 0.f, im = 0.f;
#pragma unroll
        for (int l = 0; l < 15; ++l) {
            re = fmaf(y3[l], ct[(j - 1) * 15 + l], re);
            im = fmaf(y3[l], st[(j - 1) * 15 + l], im);
        }
        float pp = re * re + im * im;
        psum += pp;
        fs    = fmaf((float)j, pp, fs);
    }

    float v0 = spb[c * 2 + 0], v1 = spb[c * 2 + 1];
#pragma unroll
    for (int l = 0; l < 15; ++l) {
        v0 = fmaf(y3[l], spw[(c * 2 + 0) * 15 + l], v0);
        v1 = fmaf(y3[l], spw[(c * 2 + 1) * 15 + l], v1);
    }

    if (valid) {
        out[(size_t)b * 24 + 6 + c]  = fs / psum;
        out[(size_t)b * 24 + 12 + c] = 2.f * sqrtf(psum) * (1.f / 15.f);
        out[(size_t)b * 24 + 18 + c] = re0 * (1.f / 15.f);
        g_v[(size_t)(2 * c + 0) * B + b] = v0;
        g_v[(size_t)(2 * c + 1) * B + b] = v1;
    } else { v0 = 0.f; v1 = 0.f; }

    float s0 = v0, q0 = v0 * v0, s1 = v1, q1 = v1 * v1;
#pragma unroll
    for (int off = 16; off; off >>= 1) {
        s0 += __shfl_down_sync(0xffffffffu, s0, off);
        q0 += __shfl_down_sync(0xffffffffu, q0, off);
        s1 += __shfl_down_sync(0xffffffffu, s1, off);
        q1 += __shfl_down_sync(0xffffffffu, q1, off);
    }
    if ((tid & 31) == 0) {
        atomicAdd(&g_vsum[2 * c + 0], (double)s0);
        atomicAdd(&g_vssq[2 * c + 0], (double)q0);
        atomicAdd(&g_vsum[2 * c + 1], (double)s1);
        atomicAdd(&g_vssq[2 * c + 1], (double)q1);
    }
}

// ---------------------------------------------------------------------------
// Kernel 7: batch-normalize v, phase = atan2(v1, v0) / (2*pi)
// ---------------------------------------------------------------------------
__global__ void k_phase(float* __restrict__ out, int B)
{
    int b = blockIdx.x * blockDim.x + threadIdx.x;
    if (b >= B) return;
    const float inv2pi = 0.15915494309189535f;
#pragma unroll
    for (int c = 0; c < 6; ++c) {
        float v0 = fmaf(g_v[(size_t)(2 * c + 0) * B + b], g_vscale[2 * c + 0], g_vshift[2 * c + 0]);
        float v1 = fmaf(g_v[(size_t)(2 * c + 1) * B + b], g_vscale[2 * c + 1], g_vshift[2 * c + 1]);
        out[(size_t)b * 24 + c] = atan2f(v1, v0) * inv2pi;
    }
}

// ---------------------------------------------------------------------------
extern "C" void kernel_launch(void* const* d_in, const int* in_sizes, int n_in,
                              void* d_out, int out_size)
{
    const float* x   = (const float*)d_in[0];
    const float* w1  = (const float*)d_in[1];
    const float* b1  = (const float*)d_in[2];
    const float* g1  = (const float*)d_in[3];
    const float* be1 = (const float*)d_in[4];
    const float* w2  = (const float*)d_in[5];
    const float* b2  = (const float*)d_in[6];
    const float* g2  = (const float*)d_in[7];
    const float* be2 = (const float*)d_in[8];
    const float* w3  = (const float*)d_in[9];
    const float* b3  = (const float*)d_in[10];
    const float* pw  = (const float*)d_in[11];
    const float* pb  = (const float*)d_in[12];
    const float* pg  = (const float*)d_in[13];
    const float* pbe = (const float*)d_in[14];
    float* out = (float*)d_out;

    const int B = in_sizes[0] / 720;

    const size_t sm1 = (size_t)(720 * 66 + 12 * 48 * 16) * sizeof(float);
    const size_t sm2 = (size_t)(720 * 66 + 12 * 48 * 16 + 96) * sizeof(float);
    const size_t sm3 = (size_t)(128 * 181 + 1152 + 180 + 210 + 6 + 12 + 12 + 12) * sizeof(float);

    cudaFuncSetAttribute(k_conv1, cudaFuncAttributeMaxDynamicSharedMemorySize, (int)sm1);
    cudaFuncSetAttribute(k_conv2, cudaFuncAttributeMaxDynamicSharedMemorySize, (int)sm2);
    cudaFuncSetAttribute(k_conv3, cudaFuncAttributeMaxDynamicSharedMemorySize, (int)sm3);

    const double invNL = 1.0 / ((double)B * 15.0);
    const double invB  = 1.0 / (double)B;

    k_zero<<<1, 64>>>();
    k_conv1<<<(B + 63) / 64, 768, sm1>>>(x, w1, b1, B);
    k_finalize<<<1, 48>>>(g1, be1, 0, 48, invNL);
    k_conv2<<<(B + 63) / 64, 768, sm2>>>(w2, b2, B);
    k_finalize<<<1, 12>>>(g2, be2, 1, 12, invNL);
    k_conv3<<<(B + 127) / 128, 768, sm3>>>(w3, b3, pw, pb, out, B);
    k_finalize<<<1, 12>>>(pg, pbe, 2, 12, invB);
    k_phase<<<(B + 255) / 256, 256>>>(out, B);
}